// round 2
// baseline (speedup 1.0000x reference)
#include <cuda_runtime.h>
#include <cstdint>
#include <cstdio>

// ---------------------------------------------------------------------------
// OLSTM: social LSTM with occupancy grid, 4094 sequential steps.
// Strategy: one cluster of 8 CTAs x 256 threads. Each CTA owns 64 gate rows
// (the i/f/g/o quadruple for 16 h-indices) with its weight slice in SMEM.
// Per step: redundant occupancy (all CTAs scan all 4096 neighbors, prefetched
// one step ahead into registers), SMEM GEMV over unified x=[emb,occ,h] (K=240
// padded), gates for owned h-slice, DSMEM broadcast of 16 new h values to all
// 8 CTAs, ONE cluster barrier, redundant output head + position update.
// ---------------------------------------------------------------------------

namespace {
constexpr int EMBD  = 64;
constexpr int HID   = 128;
constexpr int OBSL  = 2048;
constexpr int NN    = 4096;
constexpr int P1    = OBSL - 1;      // 2047 phase-1 steps
constexpr int STEPS = 4094;          // total steps / output rows
constexpr int CS    = 8;             // cluster size
constexpr int TPB   = 256;
constexpr int RPC   = 64;            // gate rows per CTA
constexpr int HPC   = 16;            // h indices per CTA
constexpr int KTOT  = 240;           // unified K (100 + 128, padded to 240)
constexpr int KP    = 60;            // K per part (4 parts of 60)
constexpr int NBT   = NN / TPB;      // 16 neighbors per thread

struct Smem {
    float Wl[KTOT * RPC];            // [k][localrow], 61440 B
    float xv[KTOT];                  // [emb(64) | occ(36) | h(128) | pad]
    float hbuf[2][HID];              // double-buffered full h
    float partial[TPB];
    float bsum[RPC];                 // b_ih + b_hh for owned rows
    float c_s[HPC];                  // cell state (owned slice)
    float W_emb_s[EMBD * 2];
    float b_emb_s[EMBD];
    float W_out_s[5 * HID];
    float b_out_s[5];
    float normal_s[5];
    float pc[2], pp[2];
    unsigned occ_lo, occ_hi;
};
} // namespace

__device__ __forceinline__ unsigned ctarank() {
    unsigned r; asm("mov.u32 %0, %%cluster_ctarank;" : "=r"(r)); return r;
}
__device__ __forceinline__ void cluster_sync_() {
    asm volatile("barrier.cluster.arrive.aligned;" ::: "memory");
    asm volatile("barrier.cluster.wait.aligned;" ::: "memory");
}
__device__ __forceinline__ void st_remote_f32(unsigned laddr, unsigned rank, float v) {
    unsigned ra;
    asm volatile("mapa.shared::cluster.u32 %0, %1, %2;" : "=r"(ra) : "r"(laddr), "r"(rank));
    asm volatile("st.shared::cluster.f32 [%0], %1;" :: "r"(ra), "f"(v) : "memory");
}
__device__ __forceinline__ float sigmoidf_(float x) {
    return 1.0f / (1.0f + expf(-x));
}

__global__ void __cluster_dims__(CS, 1, 1) __launch_bounds__(TPB, 1)
olstm_kernel(const float* __restrict__ observed,
             const float* __restrict__ other,
             const float* __restrict__ W_emb, const float* __restrict__ b_emb,
             const float* __restrict__ W_ih,  const float* __restrict__ b_ih,
             const float* __restrict__ W_hh,  const float* __restrict__ b_hh,
             const float* __restrict__ W_out, const float* __restrict__ b_out,
             float* __restrict__ out)
{
    extern __shared__ __align__(16) unsigned char smraw[];
    Smem* s = reinterpret_cast<Smem*>(smraw);
    const int tid = threadIdx.x;
    const unsigned rk = ctarank();

    // ---- preamble: load weight slices ----
    for (int idx = tid; idx < KTOT * RPC; idx += TPB) {
        int k = idx >> 6, m = idx & 63;
        int gr = (m >> 4) * HID + (int)rk * HPC + (m & 15);   // global gate row
        float v = 0.0f;
        if (k < 100)       v = W_ih[gr * 100 + k];
        else if (k < 228)  v = W_hh[gr * 128 + (k - 100)];
        s->Wl[idx] = v;                                       // [k][m]
    }
    for (int m = tid; m < RPC; m += TPB) {
        int gr = (m >> 4) * HID + (int)rk * HPC + (m & 15);
        s->bsum[m] = b_ih[gr] + b_hh[gr];
    }
    for (int i = tid; i < EMBD * 2; i += TPB) s->W_emb_s[i] = W_emb[i];
    for (int i = tid; i < EMBD; i += TPB)     s->b_emb_s[i] = b_emb[i];
    for (int i = tid; i < 5 * HID; i += TPB)  s->W_out_s[i] = W_out[i];
    if (tid < 5) s->b_out_s[tid] = b_out[tid];
    for (int i = tid; i < HID; i += TPB) s->hbuf[0][i] = 0.0f;
    if (tid < HPC) s->c_s[tid] = 0.0f;
    if (tid == 0) {
        s->occ_lo = 0u; s->occ_hi = 0u;
        s->pc[0] = s->pc[1] = s->pp[0] = s->pp[1] = 0.0f;
    }
    for (int k = 228 + tid; k < KTOT; k += TPB) s->xv[k] = 0.0f;
    __syncthreads();
    cluster_sync_();

    // ---- register prefetch of step-0 neighbors + observed ----
    const float2* oth2 = reinterpret_cast<const float2*>(other);
    float2 nb[NBT];
#pragma unroll
    for (int i = 0; i < NBT; i++) nb[i] = oth2[(size_t)1 * NN + i * TPB + tid];
    float ox0 = observed[0], oy0 = observed[1];
    float ox1 = observed[2], oy1 = observed[3];

    const int row  = tid & 63;
    const int part = tid >> 6;
    const float* wp = s->Wl + part * KP * RPC + row;

    for (int t = 0; t < STEPS; t++) {
        const int cur = t & 1, nxt = cur ^ 1;

        float cx, cy, dx, dy;
        if (t < P1) { cx = ox1; cy = oy1; dx = ox1 - ox0; dy = oy1 - oy0; }
        else        { cx = s->pc[0]; cy = s->pc[1]; dx = cx - s->pp[0]; dy = cy - s->pp[1]; }

        // ---- occupancy: strict edge compares matching JAX linspace exactly ----
        unsigned lo = 0u, hi = 0u;
#pragma unroll
        for (int i = 0; i < NBT; i++) {
            float x = nb[i].x, y = nb[i].y;
            if (fabsf(x - cx) < 1.6f && fabsf(y - cy) < 1.6f) {
                int ix = -1, iy = -1;
#pragma unroll
                for (int c = 0; c < 6; c++) {
                    float ex0 = cx + (0.5f * c - 1.5f);
                    float ex1 = cx + (0.5f * c - 1.0f);
                    if (x > ex0 && x < ex1) ix = c;
                    float ey0 = cy + (0.5f * c - 1.5f);
                    float ey1 = cy + (0.5f * c - 1.0f);
                    if (y > ey0 && y < ey1) iy = c;
                }
                if (ix >= 0 && iy >= 0) {
                    int b = ix * 6 + iy;
                    if (b < 32) lo |= 1u << b; else hi |= 1u << (b - 32);
                }
            }
        }
        lo = __reduce_or_sync(0xffffffffu, lo);
        hi = __reduce_or_sync(0xffffffffu, hi);
        if ((tid & 31) == 0) {
            if (lo) atomicOr(&s->occ_lo, lo);
            if (hi) atomicOr(&s->occ_hi, hi);
        }

        // ---- build xv: emb and h copy (occ bits after sync) ----
        if (tid < EMBD) {
            float e = fmaf(dx, s->W_emb_s[tid * 2],
                      fmaf(dy, s->W_emb_s[tid * 2 + 1], s->b_emb_s[tid]));
            s->xv[tid] = e > 0.0f ? e : 0.0f;
        } else if (tid >= 100 && tid < 100 + HID) {
            s->xv[tid] = s->hbuf[cur][tid - 100];
        }
        __syncthreads();
        if (tid >= EMBD && tid < 100) {
            int b = tid - EMBD;
            unsigned m = (b < 32) ? s->occ_lo : s->occ_hi;
            s->xv[tid] = ((m >> (b & 31)) & 1u) ? 1.0f : 0.0f;
        }
        __syncthreads();

        // ---- gate GEMV: 64 rows x 240 dims, 4 k-parts per row ----
        const float4* xq = reinterpret_cast<const float4*>(s->xv + part * KP);
        float a0 = 0.0f, a1 = 0.0f;
#pragma unroll
        for (int i4 = 0; i4 < KP / 4; i4++) {
            float4 xx = xq[i4];
            a0 = fmaf(wp[(i4 * 4 + 0) * RPC], xx.x, a0);
            a1 = fmaf(wp[(i4 * 4 + 1) * RPC], xx.y, a1);
            a0 = fmaf(wp[(i4 * 4 + 2) * RPC], xx.z, a0);
            a1 = fmaf(wp[(i4 * 4 + 3) * RPC], xx.w, a1);
        }
        s->partial[tid] = a0 + a1;
        __syncthreads();

        // ---- prefetch next step's neighbors/observed; reset occ mask ----
#pragma unroll
        for (int i = 0; i < NBT; i++)
            nb[i] = oth2[(size_t)(t + 2) * NN + i * TPB + tid];
        if (t + 1 < P1) {
            ox0 = ox1; oy0 = oy1;
            ox1 = observed[(t + 2) * 2]; oy1 = observed[(t + 2) * 2 + 1];
        }
        if (tid == 0) { s->occ_lo = 0u; s->occ_hi = 0u; }

        // ---- gates for owned h-slice, DSMEM broadcast of h_new ----
        if (tid < HPC) {
            float g[4];
#pragma unroll
            for (int q = 0; q < 4; q++) {
                int m = q * 16 + tid;
                g[q] = s->bsum[m] + s->partial[m] + s->partial[m + 64]
                     + s->partial[m + 128] + s->partial[m + 192];
            }
            float ig = sigmoidf_(g[0]);
            float fg = sigmoidf_(g[1]);
            float gg = tanhf(g[2]);
            float og = sigmoidf_(g[3]);
            float cN = fmaf(fg, s->c_s[tid], ig * gg);
            s->c_s[tid] = cN;
            float hN = og * tanhf(cN);
            unsigned la = (unsigned)__cvta_generic_to_shared(&s->hbuf[nxt][rk * HPC + tid]);
#pragma unroll
            for (int r = 0; r < CS; r++) st_remote_f32(la, (unsigned)r, hN);
        }
        cluster_sync_();   // release h_new writes, acquire peers' h_new

        // ---- output head (redundant in every CTA): normal = W_out @ h + b ----
        if (tid < 160) {
            int j = tid >> 5, ln = tid & 31;
            const float* wo = s->W_out_s + j * HID;
            const float* hn = s->hbuf[nxt];
            float v = hn[ln] * wo[ln];
            v = fmaf(hn[ln + 32], wo[ln + 32], v);
            v = fmaf(hn[ln + 64], wo[ln + 64], v);
            v = fmaf(hn[ln + 96], wo[ln + 96], v);
#pragma unroll
            for (int o = 16; o > 0; o >>= 1) v += __shfl_down_sync(0xffffffffu, v, o);
            if (ln == 0) s->normal_s[j] = v + s->b_out_s[j];
        }
        __syncthreads();
        if (tid == 0) {
            float bx = (t < P1) ? cx : s->pc[0];
            float by = (t < P1) ? cy : s->pc[1];
            s->pp[0] = s->pc[0]; s->pp[1] = s->pc[1];
            s->pc[0] = bx + s->normal_s[0];
            s->pc[1] = by + s->normal_s[1];
        }
        if (rk == 0 && tid < 5) out[(size_t)t * 5 + tid] = s->normal_s[tid];
        __syncthreads();
    }
}

extern "C" void kernel_launch(void* const* d_in, const int* in_sizes, int n_in,
                              void* d_out, int out_size) {
    (void)in_sizes; (void)n_in; (void)out_size;
    const float* observed = (const float*)d_in[0];
    const float* other    = (const float*)d_in[1];
    const float* W_emb    = (const float*)d_in[2];
    const float* b_emb    = (const float*)d_in[3];
    const float* W_ih     = (const float*)d_in[4];
    const float* b_ih     = (const float*)d_in[5];
    const float* W_hh     = (const float*)d_in[6];
    const float* b_hh     = (const float*)d_in[7];
    const float* W_out    = (const float*)d_in[8];
    const float* b_out    = (const float*)d_in[9];
    float* out = (float*)d_out;

    size_t sm = sizeof(Smem);
    cudaFuncSetAttribute(olstm_kernel, cudaFuncAttributeMaxDynamicSharedMemorySize, (int)sm);
    olstm_kernel<<<CS, TPB, sm>>>(observed, other, W_emb, b_emb, W_ih, b_ih,
                                  W_hh, b_hh, W_out, b_out, out);
}

// round 3
// speedup vs baseline: 1.5629x; 1.5629x over previous
#include <cuda_runtime.h>
#include <cstdint>

namespace {
constexpr int EMBD  = 64;
constexpr int HID   = 128;
constexpr int NN    = 4096;
constexpr int P1    = 2047;
constexpr int STEPS = 4094;
constexpr int CS    = 8;
constexpr int TPB   = 256;
constexpr int RPC   = 64;           // gate rows per CTA
constexpr int HPC   = 16;           // h indices per CTA
constexpr int NBT   = NN / TPB;     // 16 neighbors per thread

struct SmemB {
    float Wocc[36 * RPC];           // occ weight cols, [b][localrow]
    float xe[EMBD];                 // embedding vector
    float hbuf[2][HID];             // double-buffered h
    float partial[TPB];
    float gact[RPC];
    float bsum[RPC];
    float c_s[HPC];
    float W_emb_s[EMBD * 2];
    float b_emb_s[EMBD];
    float W_out_s[5 * HID];
    float b_out_s[8];
    float normal_s[8];
    float pc[2], pp[2];
    unsigned wlo[8], whi[8];
    unsigned long long mb[2];       // transaction mbarriers
};
} // namespace

__device__ float g_xih[(size_t)P1 * 512];

// ---------------- PTX helpers ----------------
__device__ __forceinline__ unsigned ctarank() {
    unsigned r; asm("mov.u32 %0, %%cluster_ctarank;" : "=r"(r)); return r;
}
__device__ __forceinline__ void cluster_sync_() {
    asm volatile("barrier.cluster.arrive.aligned;" ::: "memory");
    asm volatile("barrier.cluster.wait.aligned;" ::: "memory");
}
__device__ __forceinline__ unsigned mapa_(unsigned la, unsigned rank) {
    unsigned ra;
    asm("mapa.shared::cluster.u32 %0, %1, %2;" : "=r"(ra) : "r"(la), "r"(rank));
    return ra;
}
__device__ __forceinline__ void mbar_init(unsigned a, unsigned cnt) {
    asm volatile("mbarrier.init.shared.b64 [%0], %1;" :: "r"(a), "r"(cnt) : "memory");
}
__device__ __forceinline__ void mbar_expect(unsigned a, unsigned bytes) {
    asm volatile("mbarrier.arrive.expect_tx.shared.b64 _, [%0], %1;"
                 :: "r"(a), "r"(bytes) : "memory");
}
__device__ __forceinline__ void mbar_wait(unsigned a, unsigned parity) {
    asm volatile(
        "{\n\t.reg .pred P;\n"
        "WL%=:\n\t"
        "mbarrier.try_wait.parity.acquire.cluster.shared::cta.b64 P, [%0], %1, 0x989680;\n\t"
        "@P bra WD%=;\n\t"
        "bra WL%=;\n"
        "WD%=:\n\t}"
        :: "r"(a), "r"(parity) : "memory");
}
__device__ __forceinline__ void st_async_f32(unsigned raddr, float v, unsigned rmbar) {
    asm volatile(
        "st.async.shared::cluster.mbarrier::complete_tx::bytes.b32 [%0], %1, [%2];"
        :: "r"(raddr), "r"(__float_as_uint(v)), "r"(rmbar) : "memory");
}

// occupancy test for one neighbor: exact JAX linspace edge semantics
__device__ __forceinline__ void occ_point(float x, float y, float cx, float cy,
                                          unsigned& lo, unsigned& hi) {
    if (fabsf(x - cx) < 1.6f && fabsf(y - cy) < 1.6f) {
        int ix = -1, iy = -1;
#pragma unroll
        for (int c = 0; c < 6; c++) {
            float ex0 = cx + (0.5f * c - 1.5f);
            float ex1 = cx + (0.5f * c - 1.0f);
            if (x > ex0 && x < ex1) ix = c;
            float ey0 = cy + (0.5f * c - 1.5f);
            float ey1 = cy + (0.5f * c - 1.0f);
            if (y > ey0 && y < ey1) iy = c;
        }
        if (ix >= 0 && iy >= 0) {
            int b = ix * 6 + iy;
            if (b < 32) lo |= 1u << b; else hi |= 1u << (b - 32);
        }
    }
}

// ---------------- Kernel A: phase-1 precompute (fully parallel) ----------------
__global__ void __launch_bounds__(TPB) olstm_pre(
    const float* __restrict__ observed, const float* __restrict__ other,
    const float* __restrict__ W_emb, const float* __restrict__ b_emb,
    const float* __restrict__ W_ih)
{
    __shared__ __align__(16) float x100[100];
    __shared__ unsigned wlo[8], whi[8];
    const int t = blockIdx.x;
    const int tid = threadIdx.x;
    const float px = observed[t * 2],       py = observed[t * 2 + 1];
    const float cx = observed[(t + 1) * 2], cy = observed[(t + 1) * 2 + 1];
    const float dx = cx - px, dy = cy - py;

    const float2* oth2 = reinterpret_cast<const float2*>(other);
    unsigned lo = 0u, hi = 0u;
    for (int i = 0; i < NBT; i++) {
        float2 p = oth2[(size_t)(t + 1) * NN + i * TPB + tid];
        occ_point(p.x, p.y, cx, cy, lo, hi);
    }
    lo = __reduce_or_sync(0xffffffffu, lo);
    hi = __reduce_or_sync(0xffffffffu, hi);
    if ((tid & 31) == 0) { wlo[tid >> 5] = lo; whi[tid >> 5] = hi; }
    if (tid < EMBD) {
        float e = fmaf(dx, W_emb[tid * 2], fmaf(dy, W_emb[tid * 2 + 1], b_emb[tid]));
        x100[tid] = e > 0.0f ? e : 0.0f;
    }
    __syncthreads();
    if (tid >= 64 && tid < 100) {
        int b = tid - 64;
        unsigned fm = (b < 32)
            ? (wlo[0]|wlo[1]|wlo[2]|wlo[3]|wlo[4]|wlo[5]|wlo[6]|wlo[7])
            : (whi[0]|whi[1]|whi[2]|whi[3]|whi[4]|whi[5]|whi[6]|whi[7]);
        x100[tid] = ((fm >> (b & 31)) & 1u) ? 1.0f : 0.0f;
    }
    __syncthreads();

    const float4* xq = reinterpret_cast<const float4*>(x100);
    const float4* w0 = reinterpret_cast<const float4*>(W_ih + (size_t)tid * 100);
    const float4* w1 = reinterpret_cast<const float4*>(W_ih + (size_t)(tid + 256) * 100);
    float a0 = 0.0f, a1 = 0.0f;
#pragma unroll
    for (int i = 0; i < 25; i++) {
        float4 xx = xq[i], wa = w0[i], wb = w1[i];
        a0 = fmaf(wa.x, xx.x, a0); a0 = fmaf(wa.y, xx.y, a0);
        a0 = fmaf(wa.z, xx.z, a0); a0 = fmaf(wa.w, xx.w, a0);
        a1 = fmaf(wb.x, xx.x, a1); a1 = fmaf(wb.y, xx.y, a1);
        a1 = fmaf(wb.z, xx.z, a1); a1 = fmaf(wb.w, xx.w, a1);
    }
    // permute to consumer layout: idx = rk*64 + q*16 + j for row gr = q*128+rk*16+j
    const int r0 = tid, r1 = tid + 256;
    g_xih[(size_t)t * 512 + ((r0 >> 4) & 7) * 64 + (r0 >> 7) * 16 + (r0 & 15)] = a0;
    g_xih[(size_t)t * 512 + ((r1 >> 4) & 7) * 64 + (r1 >> 7) * 16 + (r1 & 15)] = a1;
}

// ---------------- Kernel B helpers ----------------
__device__ __forceinline__ void gates_and_send(SmemB* s, int tid, unsigned rk,
                                               int nxt, unsigned mb_c, unsigned la_h) {
    if (tid < 64) {
        float gv = s->bsum[tid] + s->partial[tid] + s->partial[tid + 64]
                 + s->partial[tid + 128] + s->partial[tid + 192];
        float av = (tid < 32 || tid >= 48) ? 1.0f / (1.0f + expf(-gv)) : tanhf(gv);
        s->gact[tid] = av;
        asm volatile("bar.sync 1, 64;" ::: "memory");
        if (tid < 16) {
            float ig = s->gact[tid],      fg = s->gact[16 + tid];
            float gg = s->gact[32 + tid], og = s->gact[48 + tid];
            float cN = fmaf(fg, s->c_s[tid], ig * gg);
            s->c_s[tid] = cN;
            float hN = og * tanhf(cN);
            unsigned dst = la_h + (unsigned)((nxt * HID + (int)rk * HPC + tid) * 4);
#pragma unroll
            for (int r = 0; r < CS; r++)
                st_async_f32(mapa_(dst, (unsigned)r), hN, mapa_(mb_c, (unsigned)r));
        }
    }
}

__device__ __forceinline__ void head_pos(SmemB* s, int tid, const float* hn,
                                         float bx, float by) {
    if (tid < 32) {
        float v0 = 0.0f, v1 = 0.0f;
#pragma unroll
        for (int i = 0; i < 4; i++) {
            float hv = hn[tid + 32 * i];
            v0 = fmaf(hv, s->W_out_s[tid + 32 * i], v0);
            v1 = fmaf(hv, s->W_out_s[HID + tid + 32 * i], v1);
        }
#pragma unroll
        for (int o = 16; o > 0; o >>= 1) {
            v0 += __shfl_down_sync(0xffffffffu, v0, o);
            v1 += __shfl_down_sync(0xffffffffu, v1, o);
        }
        if (tid == 0) {
            float n0 = v0 + s->b_out_s[0], n1 = v1 + s->b_out_s[1];
            s->normal_s[0] = n0; s->normal_s[1] = n1;
            s->pp[0] = s->pc[0]; s->pp[1] = s->pc[1];
            s->pc[0] = bx + n0;  s->pc[1] = by + n1;
        }
    } else if (tid < 128) {
        int j = (tid >> 5) + 1, ln = tid & 31;
        const float* wo = s->W_out_s + j * HID;
        float v = 0.0f;
#pragma unroll
        for (int i = 0; i < 4; i++) v = fmaf(hn[ln + 32 * i], wo[ln + 32 * i], v);
#pragma unroll
        for (int o = 16; o > 0; o >>= 1) v += __shfl_down_sync(0xffffffffu, v, o);
        if (ln == 0) s->normal_s[j] = v + s->b_out_s[j];
    }
}

// ---------------- Kernel B: sequential cluster ----------------
__global__ void __cluster_dims__(CS, 1, 1) __launch_bounds__(TPB, 1)
olstm_seq(const float* __restrict__ observed, const float* __restrict__ other,
          const float* __restrict__ W_emb, const float* __restrict__ b_emb,
          const float* __restrict__ W_ih,  const float* __restrict__ b_ih,
          const float* __restrict__ W_hh,  const float* __restrict__ b_hh,
          const float* __restrict__ W_out, const float* __restrict__ b_out,
          float* __restrict__ out)
{
    __shared__ __align__(16) SmemB s;
    const int tid = threadIdx.x;
    const unsigned rk = ctarank();
    const int m = tid & 63, part = tid >> 6;
    const int gr = (m >> 4) * HID + (int)rk * HPC + (m & 15);

    // register-resident gate weights: 16 emb cols + 32 h cols per thread
    float w[48];
#pragma unroll
    for (int i = 0; i < 16; i++) w[i] = W_ih[(size_t)gr * 100 + part * 16 + i];
#pragma unroll
    for (int i = 0; i < 32; i++) w[16 + i] = W_hh[(size_t)gr * 128 + part * 32 + i];

    for (int idx = tid; idx < 36 * RPC; idx += TPB) {
        int b = idx >> 6, mm = idx & 63;
        int g2 = (mm >> 4) * HID + (int)rk * HPC + (mm & 15);
        s.Wocc[idx] = W_ih[(size_t)g2 * 100 + 64 + b];
    }
    if (tid < RPC) s.bsum[tid] = b_ih[gr] + b_hh[gr];
    for (int i = tid; i < EMBD * 2; i += TPB) s.W_emb_s[i] = W_emb[i];
    if (tid < EMBD) s.b_emb_s[tid] = b_emb[tid];
    for (int i = tid; i < 5 * HID; i += TPB) s.W_out_s[i] = W_out[i];
    if (tid < 5) s.b_out_s[tid] = b_out[tid];
    for (int i = tid; i < HID; i += TPB) { s.hbuf[0][i] = 0.0f; s.hbuf[1][i] = 0.0f; }
    if (tid < HPC) s.c_s[tid] = 0.0f;
    if (tid == 0) { s.pc[0] = s.pc[1] = s.pp[0] = s.pp[1] = 0.0f; }

    const unsigned mb0  = (unsigned)__cvta_generic_to_shared(&s.mb[0]);
    const unsigned mb1  = mb0 + 8;
    const unsigned la_h = (unsigned)__cvta_generic_to_shared(&s.hbuf[0][0]);
    if (tid == 0) { mbar_init(mb0, 1); mbar_init(mb1, 1); mbar_expect(mb0, 512); }
    __syncthreads();
    cluster_sync_();

    const float2* oth2 = reinterpret_cast<const float2*>(other);
    float2 nb[NBT];
    float xcur = 0.0f, xnext = 0.0f;
    if (tid < 64) xcur = g_xih[(size_t)rk * 64 + tid];
    float ox1 = 0.0f, oy1 = 0.0f, onx = 0.0f, ony = 0.0f;
    if (tid == 0) { ox1 = observed[2]; oy1 = observed[3]; }

    // ================= phase 1: precomputed x, K=128 h-GEMV =================
    for (int t = 0; t < P1; t++) {
        const int cur = t & 1, nxt = cur ^ 1;
        const unsigned mb_c = (t & 1) ? mb1 : mb0;
        const unsigned mb_n = (t & 1) ? mb0 : mb1;
        if (tid == 0) {
            mbar_expect(mb_n, 512);
            if (t + 1 < P1) { onx = observed[(t + 2) * 2]; ony = observed[(t + 2) * 2 + 1]; }
        }
        if (tid < 64 && t + 1 < P1)
            xnext = g_xih[(size_t)(t + 1) * 512 + (size_t)rk * 64 + tid];

        const float4* hq = reinterpret_cast<const float4*>(s.hbuf[cur] + part * 32);
        float acc = (part == 0) ? xcur : 0.0f;
#pragma unroll
        for (int i = 0; i < 8; i++) {
            float4 hh = hq[i];
            acc = fmaf(w[16 + 4 * i], hh.x, acc); acc = fmaf(w[17 + 4 * i], hh.y, acc);
            acc = fmaf(w[18 + 4 * i], hh.z, acc); acc = fmaf(w[19 + 4 * i], hh.w, acc);
        }
        s.partial[tid] = acc;
        if (t == P1 - 1) {
#pragma unroll
            for (int i = 0; i < NBT; i++)
                nb[i] = oth2[(size_t)(P1 + 1) * NN + i * TPB + tid];
        }
        __syncthreads();
        gates_and_send(&s, tid, rk, nxt, mb_c, la_h);
        mbar_wait(mb_c, (t >> 1) & 1);
        head_pos(&s, tid, s.hbuf[nxt], ox1, oy1);
        __syncthreads();
        if (rk == 0 && tid < 5) out[(size_t)t * 5 + tid] = s.normal_s[tid];
        if (tid < 64) xcur = xnext;
        if (tid == 0) { ox1 = onx; oy1 = ony; }
    }

    // ================= phase 2: feedback, occ + emb + K=192 GEMV =================
    for (int t = P1; t < STEPS; t++) {
        const int cur = t & 1, nxt = cur ^ 1;
        const unsigned mb_c = (t & 1) ? mb1 : mb0;
        const unsigned mb_n = (t & 1) ? mb0 : mb1;
        if (tid == 0) mbar_expect(mb_n, 512);

        const float cx = s.pc[0], cy = s.pc[1];
        const float dx = cx - s.pp[0], dy = cy - s.pp[1];
        unsigned lo = 0u, hi = 0u;
#pragma unroll
        for (int i = 0; i < NBT; i++) occ_point(nb[i].x, nb[i].y, cx, cy, lo, hi);
        lo = __reduce_or_sync(0xffffffffu, lo);
        hi = __reduce_or_sync(0xffffffffu, hi);
        if ((tid & 31) == 0) { s.wlo[tid >> 5] = lo; s.whi[tid >> 5] = hi; }
        if (tid < 64) {
            float e = fmaf(dx, s.W_emb_s[tid * 2],
                      fmaf(dy, s.W_emb_s[tid * 2 + 1], s.b_emb_s[tid]));
            s.xe[tid] = e > 0.0f ? e : 0.0f;
        }
        __syncthreads();

        const float4* hq = reinterpret_cast<const float4*>(s.hbuf[cur] + part * 32);
        const float4* eq = reinterpret_cast<const float4*>(s.xe + part * 16);
        float acc = 0.0f;
#pragma unroll
        for (int i = 0; i < 4; i++) {
            float4 xx = eq[i];
            acc = fmaf(w[4 * i],     xx.x, acc); acc = fmaf(w[4 * i + 1], xx.y, acc);
            acc = fmaf(w[4 * i + 2], xx.z, acc); acc = fmaf(w[4 * i + 3], xx.w, acc);
        }
#pragma unroll
        for (int i = 0; i < 8; i++) {
            float4 hh = hq[i];
            acc = fmaf(w[16 + 4 * i], hh.x, acc); acc = fmaf(w[17 + 4 * i], hh.y, acc);
            acc = fmaf(w[18 + 4 * i], hh.z, acc); acc = fmaf(w[19 + 4 * i], hh.w, acc);
        }
        if (part == 0) {
            unsigned flo = s.wlo[0]|s.wlo[1]|s.wlo[2]|s.wlo[3]|s.wlo[4]|s.wlo[5]|s.wlo[6]|s.wlo[7];
            unsigned fhi = s.whi[0]|s.whi[1]|s.whi[2]|s.whi[3]|s.whi[4]|s.whi[5]|s.whi[6]|s.whi[7];
            while (flo) { int b = __ffs(flo) - 1; flo &= flo - 1; acc += s.Wocc[b * RPC + m]; }
            while (fhi) { int b = __ffs(fhi) - 1; fhi &= fhi - 1; acc += s.Wocc[(b + 32) * RPC + m]; }
        }
        s.partial[tid] = acc;
        if (t + 1 < STEPS) {
#pragma unroll
            for (int i = 0; i < NBT; i++)
                nb[i] = oth2[(size_t)(t + 2) * NN + i * TPB + tid];
        }
        __syncthreads();
        gates_and_send(&s, tid, rk, nxt, mb_c, la_h);
        mbar_wait(mb_c, (t >> 1) & 1);
        head_pos(&s, tid, s.hbuf[nxt], cx, cy);
        __syncthreads();
        if (rk == 0 && tid < 5) out[(size_t)t * 5 + tid] = s.normal_s[tid];
    }
}

extern "C" void kernel_launch(void* const* d_in, const int* in_sizes, int n_in,
                              void* d_out, int out_size) {
    (void)in_sizes; (void)n_in; (void)out_size;
    const float* observed = (const float*)d_in[0];
    const float* other    = (const float*)d_in[1];
    const float* W_emb    = (const float*)d_in[2];
    const float* b_emb    = (const float*)d_in[3];
    const float* W_ih     = (const float*)d_in[4];
    const float* b_ih     = (const float*)d_in[5];
    const float* W_hh     = (const float*)d_in[6];
    const float* b_hh     = (const float*)d_in[7];
    const float* W_out    = (const float*)d_in[8];
    const float* b_out    = (const float*)d_in[9];
    float* out = (float*)d_out;

    olstm_pre<<<P1, TPB>>>(observed, other, W_emb, b_emb, W_ih);
    olstm_seq<<<CS, TPB>>>(observed, other, W_emb, b_emb, W_ih, b_ih,
                           W_hh, b_hh, W_out, b_out, out);
}